// round 9
// baseline (speedup 1.0000x reference)
#include <cuda_runtime.h>

// B=4, S=1024, P=1024, E=1024, H=16, D=64, NS=2048
// out = [4,1024,1024] f32, present = [2,4,16,2048,64] f32 (packed after out)

__device__ float g_q[4096 * 1024];               // tf32, pre-scaled Q [token][1024]
__device__ float g_attn[4096 * 1024];            // tf32-rounded attn output
__device__ float g_kvt[4 * 16 * 2048 * 64];      // tf32-rounded K, [b,h,key,d]
__device__ float g_vt[4 * 16 * 64 * 2048];       // tf32-rounded V^T, [b,h,d,key]
__device__ float g_xr[4096 * 1024];              // tf32-rounded x
__device__ float g_watT[3072 * 1024];            // tf32-rounded w_attn^T [N][K]
__device__ float g_wprT[1024 * 1024];            // tf32-rounded w_proj^T [N][K]

#define LOG2E 1.44269504088896f

__device__ __forceinline__ unsigned f2tf(float x) {
    unsigned u;
    asm("cvt.rna.tf32.f32 %0, %1;" : "=r"(u) : "f"(x));
    return u;
}
__device__ __forceinline__ float ex2(float x) {
    float y;
    asm("ex2.approx.ftz.f32 %0, %1;" : "=f"(y) : "f"(x));
    return y;
}
__device__ __forceinline__ void mma_tf32(float c[4], unsigned a0, unsigned a1,
                                         unsigned a2, unsigned a3,
                                         unsigned b0, unsigned b1) {
    asm volatile(
        "mma.sync.aligned.m16n8k8.row.col.f32.tf32.tf32.f32 "
        "{%0,%1,%2,%3}, {%4,%5,%6,%7}, {%8,%9}, {%0,%1,%2,%3};\n"
        : "+f"(c[0]), "+f"(c[1]), "+f"(c[2]), "+f"(c[3])
        : "r"(a0), "r"(a1), "r"(a2), "r"(a3), "r"(b0), "r"(b1));
}
__device__ __forceinline__ void ldsm4(unsigned& r0, unsigned& r1,
                                      unsigned& r2, unsigned& r3, unsigned addr) {
    asm volatile("ldmatrix.sync.aligned.m8n8.x4.shared.b16 {%0,%1,%2,%3}, [%4];"
                 : "=r"(r0), "=r"(r1), "=r"(r2), "=r"(r3) : "r"(addr));
}
__device__ __forceinline__ void cp16(unsigned dst_smem, const void* src) {
    asm volatile("cp.async.ca.shared.global [%0], [%1], 16;\n"
                 :: "r"(dst_smem), "l"(src));
}
__device__ __forceinline__ void cp_commit() {
    asm volatile("cp.async.commit_group;\n");
}
__device__ __forceinline__ void cp_wait1() {
    asm volatile("cp.async.wait_group 1;\n");
}

// ---------------------------------------------------------------------------
// Elementwise tf32 pre-rounding
// ---------------------------------------------------------------------------
__global__ __launch_bounds__(256) void round_tf32_kernel(
    const float* __restrict__ in, float* __restrict__ out)
{
    int i = blockIdx.x * 256 + threadIdx.x;
    float4 v = *(const float4*)&in[(long)i * 4];
    float4 r;
    r.x = __uint_as_float(f2tf(v.x));
    r.y = __uint_as_float(f2tf(v.y));
    r.z = __uint_as_float(f2tf(v.z));
    r.w = __uint_as_float(f2tf(v.w));
    *(float4*)&out[(long)i * 4] = r;
}

// ---------------------------------------------------------------------------
// Round + transpose: in [K][N] -> out [N][K], tf32-rounded.
// ---------------------------------------------------------------------------
__global__ __launch_bounds__(256) void round_transpose_kernel(
    const float* __restrict__ in, float* __restrict__ out, int K, int N)
{
    __shared__ float t[32][33];
    int n0 = blockIdx.x * 32;
    int k0 = blockIdx.y * 32;
    int tx = threadIdx.x & 31, ty = threadIdx.x >> 5;
#pragma unroll
    for (int j = 0; j < 4; ++j) {
        int k = k0 + ty + j * 8;
        t[ty + j * 8][tx] = __uint_as_float(f2tf(in[(long)k * N + n0 + tx]));
    }
    __syncthreads();
#pragma unroll
    for (int j = 0; j < 4; ++j) {
        int n = n0 + ty + j * 8;
        out[(long)n * K + k0 + tx] = t[tx][ty + j * 8];
    }
}

// ---------------------------------------------------------------------------
// tf32 GEMM v4: A [M][K], Bt [N][K] both K-major row blocks. R7 scheduling
// (register prefetch, single barrier, 2 buffers); BOTH operands via ldmatrix.
// Both smem tiles: [row][16], XOR swizzle chunk ^= (row&6)>>1.
// mode 0: C = A@Bt^T + bias (fp32)
// mode 1: QKV split -> g_q (scaled tf32) / present+kvt (K) / present+vt (V)
// ---------------------------------------------------------------------------
__global__ __launch_bounds__(256, 2) void gemm4_kernel(
    const float* __restrict__ A, const float* __restrict__ Bt,
    const float* __restrict__ bias, float* __restrict__ C,
    float* __restrict__ present, float* __restrict__ kvt,
    float* __restrict__ vt, int K, int mode)
{
    __shared__ float As[2][128 * 16];
    __shared__ float Bs[2][128 * 16];

    const int tid = threadIdx.x;
    const int lane = tid & 31;
    const int wid = tid >> 5;
    const int wm = wid & 1;
    const int wn = wid >> 1;
    const int bm = blockIdx.y * 128;
    const int bn = blockIdx.x * 128;

    const int ar = tid >> 1;            // row 0..127 (same for A and B tiles)
    const int ac = (tid & 1) << 3;      // k offset 0 or 8

    const float* Ap = A + (long)(bm + ar) * K + ac;
    const float* Bp = Bt + (long)(bn + ar) * K + ac;

    const int axor = (ar & 6) >> 1;
    const int ast0 = ar * 16 + 4 * (((ac >> 2) + 0) ^ axor);
    const int ast1 = ar * 16 + 4 * (((ac >> 2) + 1) ^ axor);

    const int lrow = lane & 15;
    const int lhi = lane >> 4;
    const int lxor = (lrow & 6) >> 1;
    const unsigned as_base = (unsigned)__cvta_generic_to_shared(&As[0][0]);
    const unsigned bs_base = (unsigned)__cvta_generic_to_shared(&Bs[0][0]);
    unsigned amat[4][2], bmat[2][2];
#pragma unroll
    for (int kh = 0; kh < 2; ++kh) {
        int ch = (2 * kh + lhi) ^ lxor;
#pragma unroll
        for (int mt = 0; mt < 4; ++mt) {
            int m = wm * 64 + mt * 16 + lrow;
            amat[mt][kh] = as_base + (unsigned)((m * 16 + 4 * ch) * 4);
        }
#pragma unroll
        for (int np = 0; np < 2; ++np) {
            int n = wn * 32 + np * 16 + lrow;
            bmat[np][kh] = bs_base + (unsigned)((n * 16 + 4 * ch) * 4);
        }
    }

    float acc[4][4][4] = {};

    float4 av0 = *(const float4*)Ap;
    float4 av1 = *(const float4*)(Ap + 4);
    float4 bv0 = *(const float4*)Bp;
    float4 bv1 = *(const float4*)(Bp + 4);

    int buf = 0;
    *(float4*)&As[0][ast0] = av0;
    *(float4*)&As[0][ast1] = av1;
    *(float4*)&Bs[0][ast0] = bv0;
    *(float4*)&Bs[0][ast1] = bv1;
    __syncthreads();

    const int nIter = K / 16;
    for (int it = 0; it < nIter; ++it) {
        if (it + 1 < nIter) {
            Ap += 16;
            Bp += 16;
            av0 = *(const float4*)Ap;
            av1 = *(const float4*)(Ap + 4);
            bv0 = *(const float4*)Bp;
            bv1 = *(const float4*)(Bp + 4);
        }
        const unsigned off = (unsigned)(buf * 128 * 16 * 4);
#pragma unroll
        for (int kh = 0; kh < 2; ++kh) {
            unsigned af[4][4], bf[2][4];
#pragma unroll
            for (int mt = 0; mt < 4; ++mt)
                ldsm4(af[mt][0], af[mt][1], af[mt][2], af[mt][3], amat[mt][kh] + off);
#pragma unroll
            for (int np = 0; np < 2; ++np)
                ldsm4(bf[np][0], bf[np][1], bf[np][2], bf[np][3], bmat[np][kh] + off);
#pragma unroll
            for (int np = 0; np < 2; ++np) {
#pragma unroll
                for (int mt = 0; mt < 4; ++mt) {
                    mma_tf32(acc[mt][2 * np + 0], af[mt][0], af[mt][1], af[mt][2], af[mt][3],
                             bf[np][0], bf[np][2]);
                    mma_tf32(acc[mt][2 * np + 1], af[mt][0], af[mt][1], af[mt][2], af[mt][3],
                             bf[np][1], bf[np][3]);
                }
            }
        }
        if (it + 1 < nIter) {
            int nb = buf ^ 1;
            *(float4*)&As[nb][ast0] = av0;
            *(float4*)&As[nb][ast1] = av1;
            *(float4*)&Bs[nb][ast0] = bv0;
            *(float4*)&Bs[nb][ast1] = bv1;
            __syncthreads();
            buf = nb;
        }
    }

    // epilogue
    const int kvsel = (bn >= 2048) ? 1 : 0;
#pragma unroll
    for (int mt = 0; mt < 4; ++mt) {
        int row0 = bm + wm * 64 + mt * 16 + (lane >> 2);
#pragma unroll
        for (int nt = 0; nt < 4; ++nt) {
            int col = bn + wn * 32 + nt * 8 + 2 * (lane & 3);
            float2 bv = *(const float2*)&bias[col];
            float v00 = acc[mt][nt][0] + bv.x, v01 = acc[mt][nt][1] + bv.y;
            float v10 = acc[mt][nt][2] + bv.x, v11 = acc[mt][nt][3] + bv.y;
            if (mode == 0) {
                float2 r0 = {v00, v01}, r1 = {v10, v11};
                *(float2*)&C[(long)row0 * 1024 + col] = r0;
                *(float2*)&C[(long)(row0 + 8) * 1024 + col] = r1;
            } else if (bn < 1024) {
                const float sc = 0.125f * LOG2E;
                float2 r0, r1;
                r0.x = __uint_as_float(f2tf(v00 * sc));
                r0.y = __uint_as_float(f2tf(v01 * sc));
                r1.x = __uint_as_float(f2tf(v10 * sc));
                r1.y = __uint_as_float(f2tf(v11 * sc));
                *(float2*)&C[(long)row0 * 1024 + col] = r0;
                *(float2*)&C[(long)(row0 + 8) * 1024 + col] = r1;
            } else {
                int colk = col - 1024 - (kvsel << 10);
                int h = colk >> 6, d = colk & 63;
                int bb = row0 >> 10, sN = row0 & 1023;
                long o0 = ((((long)(kvsel * 4 + bb) * 16 + h) * 2048) + 1024 + sN) * 64 + d;
                long o1 = o0 + 8 * 64;
                float2 p0 = {v00, v01}, p1 = {v10, v11};
                *(float2*)&present[o0] = p0;
                *(float2*)&present[o1] = p1;
                if (kvsel == 0) {
                    // K: rounded copy in [b,h,key,d] (kvt has only the K half)
                    long k0 = ((((long)bb * 16 + h) * 2048) + 1024 + sN) * 64 + d;
                    float2 t0, t1;
                    t0.x = __uint_as_float(f2tf(v00));
                    t0.y = __uint_as_float(f2tf(v01));
                    t1.x = __uint_as_float(f2tf(v10));
                    t1.y = __uint_as_float(f2tf(v11));
                    *(float2*)&kvt[k0] = t0;
                    *(float2*)&kvt[k0 + 8 * 64] = t1;
                } else {
                    // V: rounded transposed copy [b,h,d,key]
                    long vb = (((long)bb * 16 + h) * 64 + d) * 2048 + 1024 + sN;
                    vt[vb]            = __uint_as_float(f2tf(v00));
                    vt[vb + 2048]     = __uint_as_float(f2tf(v01));
                    vt[vb + 8]        = __uint_as_float(f2tf(v10));
                    vt[vb + 2048 + 8] = __uint_as_float(f2tf(v11));
                }
            }
        }
    }
}

// ---------------------------------------------------------------------------
// Copy the PAST half: present (fp32) + kvt (K rounded) + vt (V^T rounded).
// ---------------------------------------------------------------------------
__global__ __launch_bounds__(256) void copy_past_kernel(
    const float* __restrict__ past, float* __restrict__ present,
    float* __restrict__ kvt, float* __restrict__ vt)
{
    int i4 = blockIdx.x * 256 + threadIdx.x;  // 0 .. 2097151
    int d4 = i4 & 15;
    int t = i4 >> 4;
    int p = t & 1023; t >>= 10;
    int h = t & 15;   t >>= 4;
    int b = t & 3;    t >>= 2;
    int kv = t;

    float4 v = *(const float4*)&past[(((long)(kv * 4 + b) * 16 + h) * 1024 + p) * 64 + d4 * 4];
    long dst = ((((long)(kv * 4 + b) * 16 + h) * 2048) + p) * 64 + d4 * 4;
    *(float4*)&present[dst] = v;
    float4 r;
    r.x = __uint_as_float(f2tf(v.x));
    r.y = __uint_as_float(f2tf(v.y));
    r.z = __uint_as_float(f2tf(v.z));
    r.w = __uint_as_float(f2tf(v.w));
    if (kv == 0) {
        long kd = ((((long)b * 16 + h) * 2048) + p) * 64 + d4 * 4;
        *(float4*)&kvt[kd] = r;
    } else {
        long vb = (((long)b * 16 + h) * 64 + d4 * 4) * 2048 + p;
        vt[vb]            = r.x;
        vt[vb + 2048]     = r.y;
        vt[vb + 2 * 2048] = r.z;
        vt[vb + 3 * 2048] = r.w;
    }
}

// ---------------------------------------------------------------------------
// Flash attention v2: all smem tiles 64-f32 rows, swizzle chunk ^= row&7;
// Q/K/V fragments all via ldmatrix. K from kvt [key][d]; V from vt [d][key].
// ---------------------------------------------------------------------------
__global__ __launch_bounds__(256, 2) void attn_kernel(
    const float* __restrict__ gq,
    const float* __restrict__ kvt,
    const float* __restrict__ vtg,
    float* __restrict__ aout)
{
    extern __shared__ float sm[];
    float* Qs = sm;                      // [128][64]
    float* Ks = Qs + 128 * 64;           // [2][64][64]
    float* Vs = Ks + 2 * 64 * 64;        // [2][64][64]  (V^T: rows=d, cols=key)

    const int tid = threadIdx.x;
    const int lane = tid & 31;
    const int w = tid >> 5;
    const int qt = blockIdx.x & 7;
    const int h  = (blockIdx.x >> 3) & 15;
    const int b  = blockIdx.x >> 7;

    const float* kbase = kvt + (long)(b * 16 + h) * (2048 * 64);
    const float* vbase = vtg + (long)(b * 16 + h) * (64 * 2048);

    const unsigned qs_base = (unsigned)__cvta_generic_to_shared(Qs);
    const unsigned ks_base = (unsigned)__cvta_generic_to_shared(Ks);
    const unsigned vs_base = (unsigned)__cvta_generic_to_shared(Vs);

    auto stage = [&](int kt, int bf) {
        const float* kp = kbase + (long)kt * 64 * 64;
        unsigned kd = ks_base + (unsigned)(bf * 64 * 64 * 4);
        unsigned vd = vs_base + (unsigned)(bf * 64 * 64 * 4);
#pragma unroll
        for (int l = 0; l < 4; ++l) {
            int idx = l * 256 + tid;             // 1024 chunks: row=idx>>4, c=idx&15
            int r = idx >> 4, c = idx & 15;
            unsigned doff = (unsigned)((r * 64 + 4 * (c ^ (r & 7))) * 4);
            cp16(kd + doff, kp + r * 64 + c * 4);
            cp16(vd + doff, vbase + (long)r * 2048 + kt * 64 + c * 4);
        }
    };

    // Q tile: 128 rows x 16 chunks
    {
        const float* qb = gq + ((long)b * 1024 + qt * 128) * 1024 + h * 64;
#pragma unroll
        for (int l = 0; l < 8; ++l) {
            int idx = l * 256 + tid;
            int r = idx >> 4, c = idx & 15;
            unsigned doff = (unsigned)((r * 64 + 4 * (c ^ (r & 7))) * 4);
            cp16(qs_base + doff, qb + (long)r * 1024 + c * 4);
        }
    }
    stage(0, 0); cp_commit();
    stage(1, 1); cp_commit();
    cp_wait1();
    __syncthreads();

    const int diag0 = 16 + 2 * qt;
    const int nkt = diag0 + 2;

    const int lrow = lane & 15;
    const int lhi = lane >> 4;
    const int swz = lrow & 7;

    // Hoist Q fragments via ldmatrix (rows 16w..16w+15)
    unsigned qf[8][4];
#pragma unroll
    for (int kk = 0; kk < 8; ++kk) {
        int ch = (2 * kk + lhi) ^ swz;
        unsigned addr = qs_base + (unsigned)(((16 * w + lrow) * 64 + 4 * ch) * 4);
        ldsm4(qf[kk][0], qf[kk][1], qf[kk][2], qf[kk][3], addr);
    }

    float o[8][4] = {};
    float m0 = -1e30f, m1 = -1e30f, l0 = 0.f, l1 = 0.f;

    const int src_a = (lane & ~3) | ((lane & 3) >> 1);
    const int src_b = src_a + 2;

    for (int kt = 0; kt < nkt; ++kt) {
        const int bf = kt & 1;
        const unsigned kbuf = ks_base + (unsigned)(bf * 64 * 64 * 4);
        const unsigned vbuf = vs_base + (unsigned)(bf * 64 * 64 * 4);

        // S = Q K^T
        float s[8][4] = {};
#pragma unroll
        for (int kk = 0; kk < 8; ++kk) {
            int ch = (2 * kk + lhi) ^ swz;
#pragma unroll
            for (int ntp = 0; ntp < 4; ++ntp) {
                unsigned b0, b1, b2, b3;
                unsigned addr = kbuf + (unsigned)(((ntp * 16 + lrow) * 64 + 4 * ch) * 4);
                ldsm4(b0, b1, b2, b3, addr);
                mma_tf32(s[2 * ntp + 0], qf[kk][0], qf[kk][1], qf[kk][2], qf[kk][3], b0, b2);
                mma_tf32(s[2 * ntp + 1], qf[kk][0], qf[kk][1], qf[kk][2], qf[kk][3], b1, b3);
            }
        }

        if (kt >= diag0) {
            int q0 = 1024 + qt * 128 + 16 * w + (lane >> 2);
            int q1 = q0 + 8;
#pragma unroll
            for (int nt = 0; nt < 8; ++nt) {
                int kc = kt * 64 + nt * 8 + 2 * (lane & 3);
                if (kc > q0)     s[nt][0] = -14427.0f;
                if (kc + 1 > q0) s[nt][1] = -14427.0f;
                if (kc > q1)     s[nt][2] = -14427.0f;
                if (kc + 1 > q1) s[nt][3] = -14427.0f;
            }
        }

        // online softmax (exp2 domain)
        {
            float mt0 = -1e30f, mt1 = -1e30f;
#pragma unroll
            for (int nt = 0; nt < 8; ++nt) {
                mt0 = fmaxf(mt0, fmaxf(s[nt][0], s[nt][1]));
                mt1 = fmaxf(mt1, fmaxf(s[nt][2], s[nt][3]));
            }
            mt0 = fmaxf(mt0, __shfl_xor_sync(0xffffffffu, mt0, 1));
            mt0 = fmaxf(mt0, __shfl_xor_sync(0xffffffffu, mt0, 2));
            mt1 = fmaxf(mt1, __shfl_xor_sync(0xffffffffu, mt1, 1));
            mt1 = fmaxf(mt1, __shfl_xor_sync(0xffffffffu, mt1, 2));
            float mn0 = fmaxf(m0, mt0), mn1 = fmaxf(m1, mt1);
            float c0 = ex2(m0 - mn0), c1 = ex2(m1 - mn1);
            m0 = mn0; m1 = mn1;
            float rs0 = 0.f, rs1 = 0.f;
#pragma unroll
            for (int nt = 0; nt < 8; ++nt) {
                s[nt][0] = ex2(s[nt][0] - mn0);
                s[nt][1] = ex2(s[nt][1] - mn0);
                s[nt][2] = ex2(s[nt][2] - mn1);
                s[nt][3] = ex2(s[nt][3] - mn1);
                rs0 += s[nt][0] + s[nt][1];
                rs1 += s[nt][2] + s[nt][3];
            }
            rs0 += __shfl_xor_sync(0xffffffffu, rs0, 1);
            rs0 += __shfl_xor_sync(0xffffffffu, rs0, 2);
            rs1 += __shfl_xor_sync(0xffffffffu, rs1, 1);
            rs1 += __shfl_xor_sync(0xffffffffu, rs1, 2);
            l0 = l0 * c0 + rs0;
            l1 = l1 * c1 + rs1;
#pragma unroll
            for (int dt = 0; dt < 8; ++dt) {
                o[dt][0] *= c0; o[dt][1] *= c0;
                o[dt][2] *= c1; o[dt][3] *= c1;
            }
        }

        // O += P @ V : A-frags via shuffle, B-frags via ldmatrix from V^T
#pragma unroll
        for (int kk = 0; kk < 8; ++kk) {
            float x0 = __shfl_sync(0xffffffffu, s[kk][0], src_a);
            float x1 = __shfl_sync(0xffffffffu, s[kk][1], src_a);
            float y0 = __shfl_sync(0xffffffffu, s[kk][2], src_a);
            float y1 = __shfl_sync(0xffffffffu, s[kk][3], src_a);
            float z0 = __shfl_sync(0xffffffffu, s[kk][0], src_b);
            float z1 = __shfl_sync(0xffffffffu, s[kk][1], src_b);
            float u0 = __shfl_sync(0xffffffffu, s[kk][2], src_b);
            float u1 = __shfl_sync(0xffffffffu, s[kk][3], src_b);
            bool odd = (lane & 1);
            unsigned a0 = f2tf(odd ? x1 : x0);
            unsigned a1 = f2tf(odd ? y1 : y0);
            unsigned a2 = f2tf(odd ? z1 : z0);
            unsigned a3 = f2tf(odd ? u1 : u0);
            int ch = (2 * kk + lhi) ^ swz;
#pragma unroll
            for (int dtp = 0; dtp < 4; ++dtp) {
                unsigned b0, b1, b2, b3;
                unsigned addr = vbuf + (unsigned)(((dtp * 16 + lrow) * 64 + 4 * ch) * 4);
                ldsm4(b0, b1, b2, b3, addr);
                mma_tf32(o[2 * dtp + 0], a0, a1, a2, a3, b0, b2);
                mma_tf32(o[2 * dtp + 1], a0, a1, a2, a3, b1, b3);
            }
        }

        if (kt + 1 < nkt) {
            __syncthreads();
            if (kt + 2 < nkt) stage(kt + 2, bf);
            cp_commit();
            cp_wait1();
            __syncthreads();
        }
    }

    // epilogue (tf32-rounded for proj GEMM)
    {
        float inv0 = 1.0f / l0, inv1 = 1.0f / l1;
        int row0 = b * 1024 + qt * 128 + 16 * w + (lane >> 2);
        float* ob = aout + (long)row0 * 1024 + h * 64;
#pragma unroll
        for (int dt = 0; dt < 8; ++dt) {
            int c = dt * 8 + 2 * (lane & 3);
            float2 v0, v1;
            v0.x = __uint_as_float(f2tf(o[dt][0] * inv0));
            v0.y = __uint_as_float(f2tf(o[dt][1] * inv0));
            v1.x = __uint_as_float(f2tf(o[dt][2] * inv1));
            v1.y = __uint_as_float(f2tf(o[dt][3] * inv1));
            *(float2*)&ob[c] = v0;
            *(float2*)&ob[(long)8 * 1024 + c] = v1;
        }
    }
}

// ---------------------------------------------------------------------------
extern "C" void kernel_launch(void* const* d_in, const int* in_sizes, int n_in,
                              void* d_out, int out_size)
{
    const float* x      = (const float*)d_in[0];
    const float* past   = (const float*)d_in[1];
    const float* w_attn = (const float*)d_in[2];
    const float* b_attn = (const float*)d_in[3];
    const float* w_proj = (const float*)d_in[4];
    const float* b_proj = (const float*)d_in[5];

    float* out = (float*)d_out;
    float* present = out + 4194304;

    float *q_p, *attn_p, *kvt_p, *vt_p, *xr_p, *watT_p, *wprT_p;
    cudaGetSymbolAddress((void**)&q_p, g_q);
    cudaGetSymbolAddress((void**)&attn_p, g_attn);
    cudaGetSymbolAddress((void**)&kvt_p, g_kvt);
    cudaGetSymbolAddress((void**)&vt_p, g_vt);
    cudaGetSymbolAddress((void**)&xr_p, g_xr);
    cudaGetSymbolAddress((void**)&watT_p, g_watT);
    cudaGetSymbolAddress((void**)&wprT_p, g_wprT);

    // 0) pre-round x; round+transpose weights to [N][K]
    round_tf32_kernel<<<4096, 256>>>(x, xr_p);
    {
        dim3 g(3072 / 32, 1024 / 32);
        round_transpose_kernel<<<g, 256>>>(w_attn, watT_p, 1024, 3072);
    }
    {
        dim3 g(1024 / 32, 1024 / 32);
        round_transpose_kernel<<<g, 256>>>(w_proj, wprT_p, 1024, 1024);
    }

    // 1) QKV projection with fused Q-scale / present / kvt / vt epilogue
    {
        dim3 grid(3072 / 128, 4096 / 128);
        gemm4_kernel<<<grid, 256>>>(xr_p, watT_p, b_attn, q_p,
                                    present, kvt_p, vt_p, 1024, 1);
    }

    // 2) past half of present/kvt/vt
    copy_past_kernel<<<2097152 / 256, 256>>>(past, present, kvt_p, vt_p);

    // 3) attention
    {
        int smem = (128 * 64 + 2 * 64 * 64 + 2 * 64 * 64) * (int)sizeof(float);
        cudaFuncSetAttribute(attn_kernel,
                             cudaFuncAttributeMaxDynamicSharedMemorySize, smem);
        attn_kernel<<<512, 256, smem>>>(q_p, kvt_p, vt_p, attn_p);
    }

    // 4) output projection
    {
        dim3 grid(1024 / 128, 4096 / 128);
        gemm4_kernel<<<grid, 256>>>(attn_p, wprT_p, b_proj, out,
                                    nullptr, nullptr, nullptr, 1024, 0);
    }
}

// round 10
// speedup vs baseline: 1.0724x; 1.0724x over previous
#include <cuda_runtime.h>

// B=4, S=1024, P=1024, E=1024, H=16, D=64, NS=2048
// out = [4,1024,1024] f32, present = [2,4,16,2048,64] f32 (packed after out)

__device__ float g_q[4096 * 1024];               // tf32, pre-scaled Q [token][1024]
__device__ float g_attn[4096 * 1024];            // tf32-rounded attn output
__device__ float g_kvt[4 * 16 * 2048 * 64];      // tf32-rounded K, [b,h,key,d]
__device__ float g_vt[4 * 16 * 64 * 2048];       // tf32-rounded V^T, [b,h,d,key]
__device__ float g_xr[4096 * 1024];              // tf32-rounded x
__device__ float g_watT[3072 * 1024];            // tf32-rounded w_attn^T [N][K]
__device__ float g_wprT[1024 * 1024];            // tf32-rounded w_proj^T [N][K]

#define LOG2E 1.44269504088896f

__device__ __forceinline__ unsigned f2tf(float x) {
    unsigned u;
    asm("cvt.rna.tf32.f32 %0, %1;" : "=r"(u) : "f"(x));
    return u;
}
__device__ __forceinline__ float ex2(float x) {
    float y;
    asm("ex2.approx.ftz.f32 %0, %1;" : "=f"(y) : "f"(x));
    return y;
}
__device__ __forceinline__ void mma_tf32(float c[4], unsigned a0, unsigned a1,
                                         unsigned a2, unsigned a3,
                                         unsigned b0, unsigned b1) {
    asm volatile(
        "mma.sync.aligned.m16n8k8.row.col.f32.tf32.tf32.f32 "
        "{%0,%1,%2,%3}, {%4,%5,%6,%7}, {%8,%9}, {%0,%1,%2,%3};\n"
        : "+f"(c[0]), "+f"(c[1]), "+f"(c[2]), "+f"(c[3])
        : "r"(a0), "r"(a1), "r"(a2), "r"(a3), "r"(b0), "r"(b1));
}
__device__ __forceinline__ void ldsm4(unsigned& r0, unsigned& r1,
                                      unsigned& r2, unsigned& r3, unsigned addr) {
    asm volatile("ldmatrix.sync.aligned.m8n8.x4.shared.b16 {%0,%1,%2,%3}, [%4];"
                 : "=r"(r0), "=r"(r1), "=r"(r2), "=r"(r3) : "r"(addr));
}
__device__ __forceinline__ void cp16(unsigned dst_smem, const void* src) {
    asm volatile("cp.async.ca.shared.global [%0], [%1], 16;\n"
                 :: "r"(dst_smem), "l"(src));
}
__device__ __forceinline__ void cp_commit() {
    asm volatile("cp.async.commit_group;\n");
}
__device__ __forceinline__ void cp_wait0() {
    asm volatile("cp.async.wait_group 0;\n");
}
__device__ __forceinline__ void cp_wait1() {
    asm volatile("cp.async.wait_group 1;\n");
}

// ---------------------------------------------------------------------------
// Elementwise tf32 pre-rounding
// ---------------------------------------------------------------------------
__global__ __launch_bounds__(256) void round_tf32_kernel(
    const float* __restrict__ in, float* __restrict__ out)
{
    int i = blockIdx.x * 256 + threadIdx.x;
    float4 v = *(const float4*)&in[(long)i * 4];
    float4 r;
    r.x = __uint_as_float(f2tf(v.x));
    r.y = __uint_as_float(f2tf(v.y));
    r.z = __uint_as_float(f2tf(v.z));
    r.w = __uint_as_float(f2tf(v.w));
    *(float4*)&out[(long)i * 4] = r;
}

// ---------------------------------------------------------------------------
// Round + transpose: in [K][N] -> out [N][K], tf32-rounded.
// ---------------------------------------------------------------------------
__global__ __launch_bounds__(256) void round_transpose_kernel(
    const float* __restrict__ in, float* __restrict__ out, int K, int N)
{
    __shared__ float t[32][33];
    int n0 = blockIdx.x * 32;
    int k0 = blockIdx.y * 32;
    int tx = threadIdx.x & 31, ty = threadIdx.x >> 5;
#pragma unroll
    for (int j = 0; j < 4; ++j) {
        int k = k0 + ty + j * 8;
        t[ty + j * 8][tx] = __uint_as_float(f2tf(in[(long)k * N + n0 + tx]));
    }
    __syncthreads();
#pragma unroll
    for (int j = 0; j < 4; ++j) {
        int n = n0 + ty + j * 8;
        out[(long)n * K + k0 + tx] = t[tx][ty + j * 8];
    }
}

// ---------------------------------------------------------------------------
// tf32 GEMM v5: 128x128 tile, 128 threads (4 warps as 2x2, warp tile 64x64).
// cp.async 3-stage ring, ONE __syncthreads per iter. Both operands via
// ldmatrix from [row][16] tiles, XOR swizzle chunk ^= (row&6)>>1.
// A [M][K], Bt [N][K]. mode 0: C=A@Bt^T+bias. mode 1: QKV split epilogue.
// ---------------------------------------------------------------------------
__global__ __launch_bounds__(128, 2) void gemm5_kernel(
    const float* __restrict__ A, const float* __restrict__ Bt,
    const float* __restrict__ bias, float* __restrict__ C,
    float* __restrict__ present, float* __restrict__ kvt,
    float* __restrict__ vt, int K, int mode)
{
    __shared__ float smp[3 * 4096];   // 3 stages x (A 2048 + B 2048 floats)

    const int tid = threadIdx.x;
    const int lane = tid & 31;
    const int wid = tid >> 5;
    const int wm = wid & 1;           // m half (64 rows)
    const int wn = wid >> 1;          // n half (64 cols)
    const int bm = blockIdx.y * 128;
    const int bn = blockIdx.x * 128;

    const unsigned sb = (unsigned)__cvta_generic_to_shared(smp);

    // fragment ldsm offsets (relative to stage base)
    const int lrow = lane & 15;
    const int lhi = lane >> 4;
    const int lxor = (lrow & 6) >> 1;
    unsigned amat[4][2], bmat[4][2];
#pragma unroll
    for (int kh = 0; kh < 2; ++kh) {
        int ch = (2 * kh + lhi) ^ lxor;
#pragma unroll
        for (int mt = 0; mt < 4; ++mt) {
            int m = wm * 64 + mt * 16 + lrow;
            amat[mt][kh] = (unsigned)((m * 16 + 4 * ch) * 4);
        }
#pragma unroll
        for (int np = 0; np < 4; ++np) {
            int n = wn * 64 + np * 16 + lrow;
            bmat[np][kh] = (unsigned)((2048 * 4) + (n * 16 + 4 * ch) * 4);
        }
    }

    // staging: thread covers 4 chunk-ids per operand: id=j*128+tid, row=id>>2, c=id&3
    auto stage = [&](int it) {
        const int s = it % 3;
        const unsigned base = sb + (unsigned)(s * 4096 * 4);
#pragma unroll
        for (int j = 0; j < 4; ++j) {
            int id = j * 128 + tid;
            int row = id >> 2, c = id & 3;
            unsigned off = (unsigned)((row * 16 + 4 * (c ^ ((row & 6) >> 1))) * 4);
            cp16(base + off, A + (long)(bm + row) * K + it * 16 + c * 4);
            cp16(base + 2048 * 4 + off, Bt + (long)(bn + row) * K + it * 16 + c * 4);
        }
    };

    float acc[4][8][4] = {};

    const int nIter = K / 16;
    stage(0); cp_commit();
    stage(1); cp_commit();

    for (int it = 0; it < nIter; ++it) {
        cp_wait1();
        __syncthreads();
        if (it + 2 < nIter) stage(it + 2);
        cp_commit();

        const unsigned base = sb + (unsigned)((it % 3) * 4096 * 4);
#pragma unroll
        for (int kh = 0; kh < 2; ++kh) {
            unsigned af[4][4];
#pragma unroll
            for (int mt = 0; mt < 4; ++mt)
                ldsm4(af[mt][0], af[mt][1], af[mt][2], af[mt][3], base + amat[mt][kh]);
#pragma unroll
            for (int np = 0; np < 4; ++np) {
                unsigned b0, b1, b2, b3;
                ldsm4(b0, b1, b2, b3, base + bmat[np][kh]);
#pragma unroll
                for (int mt = 0; mt < 4; ++mt) {
                    mma_tf32(acc[mt][2 * np + 0], af[mt][0], af[mt][1], af[mt][2], af[mt][3], b0, b2);
                    mma_tf32(acc[mt][2 * np + 1], af[mt][0], af[mt][1], af[mt][2], af[mt][3], b1, b3);
                }
            }
        }
    }

    // epilogue
    const int kvsel = (bn >= 2048) ? 1 : 0;
#pragma unroll
    for (int mt = 0; mt < 4; ++mt) {
        int row0 = bm + wm * 64 + mt * 16 + (lane >> 2);
#pragma unroll
        for (int nt = 0; nt < 8; ++nt) {
            int col = bn + wn * 64 + nt * 8 + 2 * (lane & 3);
            float2 bv = *(const float2*)&bias[col];
            float v00 = acc[mt][nt][0] + bv.x, v01 = acc[mt][nt][1] + bv.y;
            float v10 = acc[mt][nt][2] + bv.x, v11 = acc[mt][nt][3] + bv.y;
            if (mode == 0) {
                float2 r0 = {v00, v01}, r1 = {v10, v11};
                *(float2*)&C[(long)row0 * 1024 + col] = r0;
                *(float2*)&C[(long)(row0 + 8) * 1024 + col] = r1;
            } else if (bn < 1024) {
                const float sc = 0.125f * LOG2E;
                float2 r0, r1;
                r0.x = __uint_as_float(f2tf(v00 * sc));
                r0.y = __uint_as_float(f2tf(v01 * sc));
                r1.x = __uint_as_float(f2tf(v10 * sc));
                r1.y = __uint_as_float(f2tf(v11 * sc));
                *(float2*)&C[(long)row0 * 1024 + col] = r0;
                *(float2*)&C[(long)(row0 + 8) * 1024 + col] = r1;
            } else {
                int colk = col - 1024 - (kvsel << 10);
                int h = colk >> 6, d = colk & 63;
                int bb = row0 >> 10, sN = row0 & 1023;
                long o0 = ((((long)(kvsel * 4 + bb) * 16 + h) * 2048) + 1024 + sN) * 64 + d;
                long o1 = o0 + 8 * 64;
                float2 p0 = {v00, v01}, p1 = {v10, v11};
                *(float2*)&present[o0] = p0;
                *(float2*)&present[o1] = p1;
                if (kvsel == 0) {
                    long k0 = ((((long)bb * 16 + h) * 2048) + 1024 + sN) * 64 + d;
                    float2 t0, t1;
                    t0.x = __uint_as_float(f2tf(v00));
                    t0.y = __uint_as_float(f2tf(v01));
                    t1.x = __uint_as_float(f2tf(v10));
                    t1.y = __uint_as_float(f2tf(v11));
                    *(float2*)&kvt[k0] = t0;
                    *(float2*)&kvt[k0 + 8 * 64] = t1;
                } else {
                    long vb = (((long)bb * 16 + h) * 64 + d) * 2048 + 1024 + sN;
                    vt[vb]            = __uint_as_float(f2tf(v00));
                    vt[vb + 2048]     = __uint_as_float(f2tf(v01));
                    vt[vb + 8]        = __uint_as_float(f2tf(v10));
                    vt[vb + 2048 + 8] = __uint_as_float(f2tf(v11));
                }
            }
        }
    }
}

// ---------------------------------------------------------------------------
// Copy the PAST half: present (fp32) + kvt (K rounded) + vt (V^T rounded).
// ---------------------------------------------------------------------------
__global__ __launch_bounds__(256) void copy_past_kernel(
    const float* __restrict__ past, float* __restrict__ present,
    float* __restrict__ kvt, float* __restrict__ vt)
{
    int i4 = blockIdx.x * 256 + threadIdx.x;  // 0 .. 2097151
    int d4 = i4 & 15;
    int t = i4 >> 4;
    int p = t & 1023; t >>= 10;
    int h = t & 15;   t >>= 4;
    int b = t & 3;    t >>= 2;
    int kv = t;

    float4 v = *(const float4*)&past[(((long)(kv * 4 + b) * 16 + h) * 1024 + p) * 64 + d4 * 4];
    long dst = ((((long)(kv * 4 + b) * 16 + h) * 2048) + p) * 64 + d4 * 4;
    *(float4*)&present[dst] = v;
    float4 r;
    r.x = __uint_as_float(f2tf(v.x));
    r.y = __uint_as_float(f2tf(v.y));
    r.z = __uint_as_float(f2tf(v.z));
    r.w = __uint_as_float(f2tf(v.w));
    if (kv == 0) {
        long kd = ((((long)b * 16 + h) * 2048) + p) * 64 + d4 * 4;
        *(float4*)&kvt[kd] = r;
    } else {
        long vb = (((long)b * 16 + h) * 64 + d4 * 4) * 2048 + p;
        vt[vb]            = r.x;
        vt[vb + 2048]     = r.y;
        vt[vb + 2 * 2048] = r.z;
        vt[vb + 3 * 2048] = r.w;
    }
}

// ---------------------------------------------------------------------------
// Flash attention v3: R9 compute core; 3-stage cp.async ring with ONE
// __syncthreads per key tile. Q smem reused as stage buffers after hoist.
// smem = 3 x 32KB = 96KB.
// ---------------------------------------------------------------------------
__global__ __launch_bounds__(256, 2) void attn_kernel(
    const float* __restrict__ gq,
    const float* __restrict__ kvt,
    const float* __restrict__ vtg,
    float* __restrict__ aout)
{
    extern __shared__ float sm[];

    const int tid = threadIdx.x;
    const int lane = tid & 31;
    const int w = tid >> 5;
    const int qt = blockIdx.x & 7;
    const int h  = (blockIdx.x >> 3) & 15;
    const int b  = blockIdx.x >> 7;

    const float* kbase = kvt + (long)(b * 16 + h) * (2048 * 64);
    const float* vbase = vtg + (long)(b * 16 + h) * (64 * 2048);

    const unsigned sb = (unsigned)__cvta_generic_to_shared(sm);

    // stage s occupies [s*32KB, (s+1)*32KB): K tile 16KB then V tile 16KB.
    auto stage = [&](int kt) {
        const int s = kt % 3;
        const float* kp = kbase + (long)kt * 64 * 64;
        unsigned kd = sb + (unsigned)(s * 32768);
        unsigned vd = kd + 16384;
#pragma unroll
        for (int l = 0; l < 4; ++l) {
            int idx = l * 256 + tid;             // row=idx>>4 (0..63), c=idx&15
            int r = idx >> 4, c = idx & 15;
            unsigned doff = (unsigned)((r * 64 + 4 * (c ^ (r & 7))) * 4);
            cp16(kd + doff, kp + r * 64 + c * 4);
            cp16(vd + doff, vbase + (long)r * 2048 + kt * 64 + c * 4);
        }
    };

    // Q tile staged at sb (32KB), hoisted to registers, then overwritten.
    {
        const float* qb = gq + ((long)b * 1024 + qt * 128) * 1024 + h * 64;
#pragma unroll
        for (int l = 0; l < 8; ++l) {
            int idx = l * 256 + tid;
            int r = idx >> 4, c = idx & 15;
            unsigned doff = (unsigned)((r * 64 + 4 * (c ^ (r & 7))) * 4);
            cp16(sb + doff, qb + (long)r * 1024 + c * 4);
        }
    }
    cp_commit();
    cp_wait0();
    __syncthreads();

    const int lrow = lane & 15;
    const int lhi = lane >> 4;
    const int swz = lrow & 7;

    unsigned qf[8][4];
#pragma unroll
    for (int kk = 0; kk < 8; ++kk) {
        int ch = (2 * kk + lhi) ^ swz;
        unsigned addr = sb + (unsigned)(((16 * w + lrow) * 64 + 4 * ch) * 4);
        ldsm4(qf[kk][0], qf[kk][1], qf[kk][2], qf[kk][3], addr);
    }
    __syncthreads();   // everyone done reading Q; stage buffers may overwrite

    const int diag0 = 16 + 2 * qt;
    const int nkt = diag0 + 2;

    stage(0); cp_commit();
    stage(1); cp_commit();

    float o[8][4] = {};
    float m0 = -1e30f, m1 = -1e30f, l0 = 0.f, l1 = 0.f;

    const int src_a = (lane & ~3) | ((lane & 3) >> 1);
    const int src_b = src_a + 2;

    for (int kt = 0; kt < nkt; ++kt) {
        cp_wait1();
        __syncthreads();
        if (kt + 2 < nkt) stage(kt + 2);
        cp_commit();

        const unsigned kbuf = sb + (unsigned)((kt % 3) * 32768);
        const unsigned vbuf = kbuf + 16384;

        // S = Q K^T
        float s[8][4] = {};
#pragma unroll
        for (int kk = 0; kk < 8; ++kk) {
            int ch = (2 * kk + lhi) ^ swz;
#pragma unroll
            for (int ntp = 0; ntp < 4; ++ntp) {
                unsigned b0, b1, b2, b3;
                unsigned addr = kbuf + (unsigned)(((ntp * 16 + lrow) * 64 + 4 * ch) * 4);
                ldsm4(b0, b1, b2, b3, addr);
                mma_tf32(s[2 * ntp + 0], qf[kk][0], qf[kk][1], qf[kk][2], qf[kk][3], b0, b2);
                mma_tf32(s[2 * ntp + 1], qf[kk][0], qf[kk][1], qf[kk][2], qf[kk][3], b1, b3);
            }
        }

        if (kt >= diag0) {
            int q0 = 1024 + qt * 128 + 16 * w + (lane >> 2);
            int q1 = q0 + 8;
#pragma unroll
            for (int nt = 0; nt < 8; ++nt) {
                int kc = kt * 64 + nt * 8 + 2 * (lane & 3);
                if (kc > q0)     s[nt][0] = -14427.0f;
                if (kc + 1 > q0) s[nt][1] = -14427.0f;
                if (kc > q1)     s[nt][2] = -14427.0f;
                if (kc + 1 > q1) s[nt][3] = -14427.0f;
            }
        }

        // online softmax (exp2 domain)
        {
            float mt0 = -1e30f, mt1 = -1e30f;
#pragma unroll
            for (int nt = 0; nt < 8; ++nt) {
                mt0 = fmaxf(mt0, fmaxf(s[nt][0], s[nt][1]));
                mt1 = fmaxf(mt1, fmaxf(s[nt][2], s[nt][3]));
            }
            mt0 = fmaxf(mt0, __shfl_xor_sync(0xffffffffu, mt0, 1));
            mt0 = fmaxf(mt0, __shfl_xor_sync(0xffffffffu, mt0, 2));
            mt1 = fmaxf(mt1, __shfl_xor_sync(0xffffffffu, mt1, 1));
            mt1 = fmaxf(mt1, __shfl_xor_sync(0xffffffffu, mt1, 2));
            float mn0 = fmaxf(m0, mt0), mn1 = fmaxf(m1, mt1);
            float c0 = ex2(m0 - mn0), c1 = ex2(m1 - mn1);
            m0 = mn0; m1 = mn1;
            float rs0 = 0.f, rs1 = 0.f;
#pragma unroll
            for (int nt = 0; nt < 8; ++nt) {
                s[nt][0] = ex2(s[nt][0] - mn0);
                s[nt][1] = ex2(s[nt][1] - mn0);
                s[nt][2] = ex2(s[nt][2] - mn1);
                s[nt][3] = ex2(s[nt][3] - mn1);
                rs0 += s[nt][0] + s[nt][1];
                rs1 += s[nt][2] + s[nt][3];
            }
            rs0 += __shfl_xor_sync(0xffffffffu, rs0, 1);
            rs0 += __shfl_xor_sync(0xffffffffu, rs0, 2);
            rs1 += __shfl_xor_sync(0xffffffffu, rs1, 1);
            rs1 += __shfl_xor_sync(0xffffffffu, rs1, 2);
            l0 = l0 * c0 + rs0;
            l1 = l1 * c1 + rs1;
#pragma unroll
            for (int dt = 0; dt < 8; ++dt) {
                o[dt][0] *= c0; o[dt][1] *= c0;
                o[dt][2] *= c1; o[dt][3] *= c1;
            }
        }

        // O += P @ V : A-frags via shuffle, B-frags via ldmatrix from V^T
#pragma unroll
        for (int kk = 0; kk < 8; ++kk) {
            float x0 = __shfl_sync(0xffffffffu, s[kk][0], src_a);
            float x1 = __shfl_sync(0xffffffffu, s[kk][1], src_a);
            float y0 = __shfl_sync(0xffffffffu, s[kk][2], src_a);
            float y1 = __shfl_sync(0xffffffffu, s[kk][3], src_a);
            float z0 = __shfl_sync(0xffffffffu, s[kk][0], src_b);
            float z1 = __shfl_sync(0xffffffffu, s[kk][1], src_b);
            float u0 = __shfl_sync(0xffffffffu, s[kk][2], src_b);
            float u1 = __shfl_sync(0xffffffffu, s[kk][3], src_b);
            bool odd = (lane & 1);
            unsigned a0 = f2tf(odd ? x1 : x0);
            unsigned a1 = f2tf(odd ? y1 : y0);
            unsigned a2 = f2tf(odd ? z1 : z0);
            unsigned a3 = f2tf(odd ? u1 : u0);
            int ch = (2 * kk + lhi) ^ swz;
#pragma unroll
            for (int dtp = 0; dtp < 4; ++dtp) {
                unsigned b0, b1, b2, b3;
                unsigned addr = vbuf + (unsigned)(((dtp * 16 + lrow) * 64 + 4 * ch) * 4);
                ldsm4(b0, b1, b2, b3, addr);
                mma_tf32(o[2 * dtp + 0], a0, a1, a2, a3, b0, b2);
                mma_tf32(o[2 * dtp + 1], a0, a1, a2, a3, b1, b3);
            }
        }
    }

    // epilogue (tf32-rounded for proj GEMM)
    {
        float inv0 = 1.0f / l0, inv1 = 1.0f / l1;
        int row0 = b * 1024 + qt * 128 + 16 * w + (lane >> 2);
        float* ob = aout + (long)row0 * 1024 + h * 64;
#pragma unroll
        for (int dt = 0; dt < 8; ++dt) {
            int c = dt * 8 + 2 * (lane & 3);
            float2 v0, v1;
            v0.x = __uint_as_float(f2tf(o[dt][0] * inv0));
            v0.y = __uint_as_float(f2tf(o[dt][1] * inv0));
            v1.x = __uint_as_float(f2tf(o[dt][2] * inv1));
            v1.y = __uint_as_float(f2tf(o[dt][3] * inv1));
            *(float2*)&ob[c] = v0;
            *(float2*)&ob[(long)8 * 1024 + c] = v1;
        }
    }
}

// ---------------------------------------------------------------------------
extern "C" void kernel_launch(void* const* d_in, const int* in_sizes, int n_in,
                              void* d_out, int out_size)
{
    const float* x      = (const float*)d_in[0];
    const float* past   = (const float*)d_in[1];
    const float* w_attn = (const float*)d_in[2];
    const float* b_attn = (const float*)d_in[3];
    const float* w_proj = (const float*)d_in[4];
    const float* b_proj = (const float*)d_in[5];

    float* out = (float*)d_out;
    float* present = out + 4194304;

    float *q_p, *attn_p, *kvt_p, *vt_p, *xr_p, *watT_p, *wprT_p;
    cudaGetSymbolAddress((void**)&q_p, g_q);
    cudaGetSymbolAddress((void**)&attn_p, g_attn);
    cudaGetSymbolAddress((void**)&kvt_p, g_kvt);
    cudaGetSymbolAddress((void**)&vt_p, g_vt);
    cudaGetSymbolAddress((void**)&xr_p, g_xr);
    cudaGetSymbolAddress((void**)&watT_p, g_watT);
    cudaGetSymbolAddress((void**)&wprT_p, g_wprT);

    // 0) pre-round x; round+transpose weights to [N][K]
    round_tf32_kernel<<<4096, 256>>>(x, xr_p);
    {
        dim3 g(3072 / 32, 1024 / 32);
        round_transpose_kernel<<<g, 256>>>(w_attn, watT_p, 1024, 3072);
    }
    {
        dim3 g(1024 / 32, 1024 / 32);
        round_transpose_kernel<<<g, 256>>>(w_proj, wprT_p, 1024, 1024);
    }

    // 1) QKV projection with fused Q-scale / present / kvt / vt epilogue
    {
        dim3 grid(3072 / 128, 4096 / 128);
        gemm5_kernel<<<grid, 128>>>(xr_p, watT_p, b_attn, q_p,
                                    present, kvt_p, vt_p, 1024, 1);
    }

    // 2) past half of present/kvt/vt
    copy_past_kernel<<<2097152 / 256, 256>>>(past, present, kvt_p, vt_p);

    // 3) attention
    {
        int smem = 3 * 32768;   // 96KB
        cudaFuncSetAttribute(attn_kernel,
                             cudaFuncAttributeMaxDynamicSharedMemorySize, smem);
        attn_kernel<<<512, 256, smem>>>(q_p, kvt_p, vt_p, attn_p);
    }

    // 4) output projection
    {
        dim3 grid(1024 / 128, 4096 / 128);
        gemm5_kernel<<<grid, 128>>>(attn_p, wprT_p, b_proj, out,
                                    nullptr, nullptr, nullptr, 1024, 0);
    }
}

// round 11
// speedup vs baseline: 1.9891x; 1.8548x over previous
#include <cuda_runtime.h>
#include <cuda_fp16.h>

// B=4, S=1024, P=1024, E=1024, H=16, D=64, NS=2048
// out = [4,1024,1024] f32, present = [2,4,16,2048,64] f32 (packed after out)

__device__ __half g_qh[4096 * 1024];              // fp16, pre-scaled Q [token][1024]
__device__ __half g_ah[4096 * 1024];              // fp16 attn output
__device__ __half g_kh[4 * 16 * 2048 * 64];       // fp16 K, [b,h,key,d]
__device__ __half g_vth[4 * 16 * 64 * 2048];      // fp16 V^T, [b,h,d,key]
__device__ __half g_xh[4096 * 1024];              // fp16 x
__device__ __half g_wath[3072 * 1024];            // fp16 w_attn^T [N][K]
__device__ __half g_wprh[1024 * 1024];            // fp16 w_proj^T [N][K]

#define LOG2E 1.44269504088896f

__device__ __forceinline__ float ex2(float x) {
    float y;
    asm("ex2.approx.ftz.f32 %0, %1;" : "=f"(y) : "f"(x));
    return y;
}
__device__ __forceinline__ unsigned h2(float a, float b) {
    __half2 h = __floats2half2_rn(a, b);
    return *(unsigned*)&h;
}
__device__ __forceinline__ void mma_f16(float c[4], unsigned a0, unsigned a1,
                                        unsigned a2, unsigned a3,
                                        unsigned b0, unsigned b1) {
    asm volatile(
        "mma.sync.aligned.m16n8k16.row.col.f32.f16.f16.f32 "
        "{%0,%1,%2,%3}, {%4,%5,%6,%7}, {%8,%9}, {%0,%1,%2,%3};\n"
        : "+f"(c[0]), "+f"(c[1]), "+f"(c[2]), "+f"(c[3])
        : "r"(a0), "r"(a1), "r"(a2), "r"(a3), "r"(b0), "r"(b1));
}
__device__ __forceinline__ void ldsm4(unsigned& r0, unsigned& r1,
                                      unsigned& r2, unsigned& r3, unsigned addr) {
    asm volatile("ldmatrix.sync.aligned.m8n8.x4.shared.b16 {%0,%1,%2,%3}, [%4];"
                 : "=r"(r0), "=r"(r1), "=r"(r2), "=r"(r3) : "r"(addr));
}
__device__ __forceinline__ void cp16(unsigned dst_smem, const void* src) {
    asm volatile("cp.async.ca.shared.global [%0], [%1], 16;\n"
                 :: "r"(dst_smem), "l"(src));
}
__device__ __forceinline__ void cp_commit() {
    asm volatile("cp.async.commit_group;\n");
}
__device__ __forceinline__ void cp_wait0() {
    asm volatile("cp.async.wait_group 0;\n");
}
__device__ __forceinline__ void cp_wait1() {
    asm volatile("cp.async.wait_group 1;\n");
}

// ---------------------------------------------------------------------------
// fp32 -> fp16 rounding (4 elements/thread)
// ---------------------------------------------------------------------------
__global__ __launch_bounds__(256) void round_half_kernel(
    const float* __restrict__ in, __half* __restrict__ out)
{
    int i = blockIdx.x * 256 + threadIdx.x;
    float4 v = *(const float4*)&in[(long)i * 4];
    uint2 r;
    r.x = h2(v.x, v.y);
    r.y = h2(v.z, v.w);
    *(uint2*)&out[(long)i * 4] = r;
}

// ---------------------------------------------------------------------------
// Round + transpose: in [K][N] fp32 -> out [N][K] fp16.
// ---------------------------------------------------------------------------
__global__ __launch_bounds__(256) void round_transpose_half_kernel(
    const float* __restrict__ in, __half* __restrict__ out, int K, int N)
{
    __shared__ float t[32][33];
    int n0 = blockIdx.x * 32;
    int k0 = blockIdx.y * 32;
    int tx = threadIdx.x & 31, ty = threadIdx.x >> 5;
#pragma unroll
    for (int j = 0; j < 4; ++j) {
        int k = k0 + ty + j * 8;
        t[ty + j * 8][tx] = in[(long)k * N + n0 + tx];
    }
    __syncthreads();
#pragma unroll
    for (int j = 0; j < 4; ++j) {
        int n = n0 + ty + j * 8;
        out[(long)n * K + k0 + tx] = __float2half_rn(t[tx][ty + j * 8]);
    }
}

// ---------------------------------------------------------------------------
// fp16 GEMM: 128x128 tile, 128 threads (4 warps 2x2, warp 64x64), BK=32.
// 3-stage cp.async ring, one barrier/iter, both operands via ldmatrix.
// Smem rows: 32 halves (64B) = 4 chunks, swizzle chunk ^= (row>>1)&3.
// A [M][K] fp16, Bt [N][K] fp16.
// mode 0: C(fp32) = A@Bt^T + bias.
// mode 1: QKV split -> g_qh (scaled fp16) / present(fp32)+g_kh / +g_vth.
// ---------------------------------------------------------------------------
__global__ __launch_bounds__(128, 2) void gemm6_kernel(
    const __half* __restrict__ A, const __half* __restrict__ Bt,
    const float* __restrict__ bias, void* __restrict__ Cout,
    float* __restrict__ present, __half* __restrict__ kvh,
    __half* __restrict__ vth, int K, int mode)
{
    __shared__ __align__(16) __half smp[3 * 8192];  // 3 x (A 4096 + B 4096) halves

    const int tid = threadIdx.x;
    const int lane = tid & 31;
    const int wid = tid >> 5;
    const int wm = wid & 1;
    const int wn = wid >> 1;
    const int bm = blockIdx.y * 128;
    const int bn = blockIdx.x * 128;

    const unsigned sb = (unsigned)__cvta_generic_to_shared(smp);

    const int lrow = lane & 15;
    const int lhi = lane >> 4;

    // fragment ldsm byte offsets (relative to stage base)
    unsigned amat[4][2], bmat[4][2];
#pragma unroll
    for (int ks = 0; ks < 2; ++ks) {
#pragma unroll
        for (int mt = 0; mt < 4; ++mt) {
            int m = wm * 64 + mt * 16 + lrow;
            int ch = (2 * ks + lhi) ^ ((m >> 1) & 3);
            amat[mt][ks] = (unsigned)(m * 64 + 16 * ch);
        }
#pragma unroll
        for (int np = 0; np < 4; ++np) {
            int n = wn * 64 + np * 16 + lrow;
            int ch = (2 * ks + lhi) ^ ((n >> 1) & 3);
            bmat[np][ks] = (unsigned)(8192 + n * 64 + 16 * ch);
        }
    }

    // staging: 512 chunks per operand, 4 per thread each
    auto stage = [&](int it) {
        const unsigned base = sb + (unsigned)((it % 3) * 16384);
#pragma unroll
        for (int j = 0; j < 4; ++j) {
            int id = j * 128 + tid;
            int row = id >> 2, c = id & 3;
            unsigned off = (unsigned)(row * 64 + 16 * (c ^ ((row >> 1) & 3)));
            cp16(base + off, A + (long)(bm + row) * K + it * 32 + c * 8);
            cp16(base + 8192 + off, Bt + (long)(bn + row) * K + it * 32 + c * 8);
        }
    };

    float acc[4][8][4] = {};

    const int nIter = K / 32;
    stage(0); cp_commit();
    stage(1); cp_commit();

    for (int it = 0; it < nIter; ++it) {
        cp_wait1();
        __syncthreads();
        if (it + 2 < nIter) stage(it + 2);
        cp_commit();

        const unsigned base = sb + (unsigned)((it % 3) * 16384);
#pragma unroll
        for (int ks = 0; ks < 2; ++ks) {
            unsigned af[4][4];
#pragma unroll
            for (int mt = 0; mt < 4; ++mt)
                ldsm4(af[mt][0], af[mt][1], af[mt][2], af[mt][3], base + amat[mt][ks]);
#pragma unroll
            for (int np = 0; np < 4; ++np) {
                unsigned b0, b1, b2, b3;
                ldsm4(b0, b1, b2, b3, base + bmat[np][ks]);
#pragma unroll
                for (int mt = 0; mt < 4; ++mt) {
                    mma_f16(acc[mt][2 * np + 0], af[mt][0], af[mt][1], af[mt][2], af[mt][3], b0, b2);
                    mma_f16(acc[mt][2 * np + 1], af[mt][0], af[mt][1], af[mt][2], af[mt][3], b1, b3);
                }
            }
        }
    }

    // epilogue
    const int kvsel = (bn >= 2048) ? 1 : 0;
#pragma unroll
    for (int mt = 0; mt < 4; ++mt) {
        int row0 = bm + wm * 64 + mt * 16 + (lane >> 2);
#pragma unroll
        for (int nt = 0; nt < 8; ++nt) {
            int col = bn + wn * 64 + nt * 8 + 2 * (lane & 3);
            float2 bv = *(const float2*)&bias[col];
            float v00 = acc[mt][nt][0] + bv.x, v01 = acc[mt][nt][1] + bv.y;
            float v10 = acc[mt][nt][2] + bv.x, v11 = acc[mt][nt][3] + bv.y;
            if (mode == 0) {
                float* C = (float*)Cout;
                float2 r0 = {v00, v01}, r1 = {v10, v11};
                *(float2*)&C[(long)row0 * 1024 + col] = r0;
                *(float2*)&C[(long)(row0 + 8) * 1024 + col] = r1;
            } else if (bn < 1024) {
                __half* C = (__half*)Cout;
                const float sc = 0.125f * LOG2E;
                unsigned r0 = h2(v00 * sc, v01 * sc);
                unsigned r1 = h2(v10 * sc, v11 * sc);
                *(unsigned*)&C[(long)row0 * 1024 + col] = r0;
                *(unsigned*)&C[(long)(row0 + 8) * 1024 + col] = r1;
            } else {
                int colk = col - 1024 - (kvsel << 10);
                int h = colk >> 6, d = colk & 63;
                int bb = row0 >> 10, sN = row0 & 1023;
                long o0 = ((((long)(kvsel * 4 + bb) * 16 + h) * 2048) + 1024 + sN) * 64 + d;
                long o1 = o0 + 8 * 64;
                float2 p0 = {v00, v01}, p1 = {v10, v11};
                *(float2*)&present[o0] = p0;
                *(float2*)&present[o1] = p1;
                if (kvsel == 0) {
                    long k0 = ((((long)bb * 16 + h) * 2048) + 1024 + sN) * 64 + d;
                    *(unsigned*)&kvh[k0] = h2(v00, v01);
                    *(unsigned*)&kvh[k0 + 8 * 64] = h2(v10, v11);
                } else {
                    long vb = (((long)bb * 16 + h) * 64 + d) * 2048 + 1024 + sN;
                    vth[vb]            = __float2half_rn(v00);
                    vth[vb + 2048]     = __float2half_rn(v01);
                    vth[vb + 8]        = __float2half_rn(v10);
                    vth[vb + 2048 + 8] = __float2half_rn(v11);
                }
            }
        }
    }
}

// ---------------------------------------------------------------------------
// Copy PAST half: present (fp32) + g_kh (fp16 [key][d]) + g_vth (fp16 [d][key]).
// ---------------------------------------------------------------------------
__global__ __launch_bounds__(256) void copy_past_kernel(
    const float* __restrict__ past, float* __restrict__ present,
    __half* __restrict__ kvh, __half* __restrict__ vth)
{
    int i4 = blockIdx.x * 256 + threadIdx.x;  // 0 .. 2097151
    int d4 = i4 & 15;
    int t = i4 >> 4;
    int p = t & 1023; t >>= 10;
    int h = t & 15;   t >>= 4;
    int b = t & 3;    t >>= 2;
    int kv = t;

    float4 v = *(const float4*)&past[(((long)(kv * 4 + b) * 16 + h) * 1024 + p) * 64 + d4 * 4];
    long dst = ((((long)(kv * 4 + b) * 16 + h) * 2048) + p) * 64 + d4 * 4;
    *(float4*)&present[dst] = v;
    if (kv == 0) {
        long kd = ((((long)b * 16 + h) * 2048) + p) * 64 + d4 * 4;
        uint2 r;
        r.x = h2(v.x, v.y);
        r.y = h2(v.z, v.w);
        *(uint2*)&kvh[kd] = r;
    } else {
        long vb = (((long)b * 16 + h) * 64 + d4 * 4) * 2048 + p;
        vth[vb]            = __float2half_rn(v.x);
        vth[vb + 2048]     = __float2half_rn(v.y);
        vth[vb + 2 * 2048] = __float2half_rn(v.z);
        vth[vb + 3 * 2048] = __float2half_rn(v.w);
    }
}

// ---------------------------------------------------------------------------
// Flash attention fp16: 3-stage cp.async ring (one barrier/tile), all operand
// fragments via ldmatrix, P->A fragment conversion is free (pack half2).
// Smem: 3 x (K 8KB + V 8KB) = 48KB; Q staged in stage-0 region then hoisted.
// Rows 128B (8 chunks), swizzle chunk ^= row&7.
// ---------------------------------------------------------------------------
__global__ __launch_bounds__(256, 2) void attn_kernel(
    const __half* __restrict__ gq,
    const __half* __restrict__ kvh,
    const __half* __restrict__ vtg,
    __half* __restrict__ aout)
{
    __shared__ __align__(16) __half smh[3 * 8192];

    const int tid = threadIdx.x;
    const int lane = tid & 31;
    const int w = tid >> 5;
    const int qt = blockIdx.x & 7;
    const int h  = (blockIdx.x >> 3) & 15;
    const int b  = blockIdx.x >> 7;

    const __half* kbase = kvh + (long)(b * 16 + h) * (2048 * 64);
    const __half* vbase = vtg + (long)(b * 16 + h) * (64 * 2048);

    const unsigned sb = (unsigned)__cvta_generic_to_shared(smh);

    // stage s: K tile (64x64 halves, 8KB) then V tile (8KB)
    auto stage = [&](int kt) {
        const int s = kt % 3;
        const __half* kp = kbase + (long)kt * 64 * 64;
        unsigned kd = sb + (unsigned)(s * 16384);
        unsigned vd = kd + 8192;
#pragma unroll
        for (int l = 0; l < 2; ++l) {
            int idx = l * 256 + tid;            // 512 chunks: row=idx>>3, c=idx&7
            int r = idx >> 3, c = idx & 7;
            unsigned doff = (unsigned)(r * 128 + 16 * (c ^ (r & 7)));
            cp16(kd + doff, kp + r * 64 + c * 8);
            cp16(vd + doff, vbase + (long)r * 2048 + kt * 64 + c * 8);
        }
    };

    // Q tile (128 rows x 64 halves = 16KB) staged at sb, then hoisted.
    {
        const __half* qb = gq + ((long)b * 1024 + qt * 128) * 1024 + h * 64;
#pragma unroll
        for (int l = 0; l < 4; ++l) {
            int idx = l * 256 + tid;            // 1024 chunks
            int r = idx >> 3, c = idx & 7;
            unsigned doff = (unsigned)(r * 128 + 16 * (c ^ (r & 7)));
            cp16(sb + doff, qb + (long)r * 1024 + c * 8);
        }
    }
    cp_commit();
    cp_wait0();
    __syncthreads();

    const int lrow = lane & 15;
    const int lhi = lane >> 4;

    // Hoist Q fragments: 4 k-steps (d=64/16), rows 16w..16w+15
    unsigned qf[4][4];
#pragma unroll
    for (int ks = 0; ks < 4; ++ks) {
        int m = 16 * w + lrow;
        int ch = (2 * ks + lhi) ^ (m & 7);
        ldsm4(qf[ks][0], qf[ks][1], qf[ks][2], qf[ks][3],
              sb + (unsigned)(m * 128 + 16 * ch));
    }
    __syncthreads();   // Q reads done; ring may overwrite

    const int diag0 = 16 + 2 * qt;
    const int nkt = diag0 + 2;

    stage(0); cp_commit();
    stage(1); cp_commit();

    float o[8][4] = {};
    float m0 = -1e30f, m1 = -1e30f, l0 = 0.f, l1 = 0.f;

    for (int kt = 0; kt < nkt; ++kt) {
        cp_wait1();
        __syncthreads();
        if (kt + 2 < nkt) stage(kt + 2);
        cp_commit();

        const unsigned kbuf = sb + (unsigned)((kt % 3) * 16384);
        const unsigned vbuf = kbuf + 8192;

        // S = Q K^T : 4 k-steps over d, 4 np (16 keys each)
        float s[8][4] = {};
#pragma unroll
        for (int ks = 0; ks < 4; ++ks) {
#pragma unroll
            for (int np = 0; np < 4; ++np) {
                int n = np * 16 + lrow;
                int ch = (2 * ks + lhi) ^ (n & 7);
                unsigned b0, b1, b2, b3;
                ldsm4(b0, b1, b2, b3, kbuf + (unsigned)(n * 128 + 16 * ch));
                mma_f16(s[2 * np + 0], qf[ks][0], qf[ks][1], qf[ks][2], qf[ks][3], b0, b2);
                mma_f16(s[2 * np + 1], qf[ks][0], qf[ks][1], qf[ks][2], qf[ks][3], b1, b3);
            }
        }

        if (kt >= diag0) {
            int q0 = 1024 + qt * 128 + 16 * w + (lane >> 2);
            int q1 = q0 + 8;
#pragma unroll
            for (int nt = 0; nt < 8; ++nt) {
                int kc = kt * 64 + nt * 8 + 2 * (lane & 3);
                if (kc > q0)     s[nt][0] = -14427.0f;
                if (kc + 1 > q0) s[nt][1] = -14427.0f;
                if (kc > q1)     s[nt][2] = -14427.0f;
                if (kc + 1 > q1) s[nt][3] = -14427.0f;
            }
        }

        // online softmax (exp2 domain)
        {
            float mt0 = -1e30f, mt1 = -1e30f;
#pragma unroll
            for (int nt = 0; nt < 8; ++nt) {
                mt0 = fmaxf(mt0, fmaxf(s[nt][0], s[nt][1]));
                mt1 = fmaxf(mt1, fmaxf(s[nt][2], s[nt][3]));
            }
            mt0 = fmaxf(mt0, __shfl_xor_sync(0xffffffffu, mt0, 1));
            mt0 = fmaxf(mt0, __shfl_xor_sync(0xffffffffu, mt0, 2));
            mt1 = fmaxf(mt1, __shfl_xor_sync(0xffffffffu, mt1, 1));
            mt1 = fmaxf(mt1, __shfl_xor_sync(0xffffffffu, mt1, 2));
            float mn0 = fmaxf(m0, mt0), mn1 = fmaxf(m1, mt1);
            float c0 = ex2(m0 - mn0), c1 = ex2(m1 - mn1);
            m0 = mn0; m1 = mn1;
            float rs0 = 0.f, rs1 = 0.f;
#pragma unroll
            for (int nt = 0; nt < 8; ++nt) {
                s[nt][0] = ex2(s[nt][0] - mn0);
                s[nt][1] = ex2(s[nt][1] - mn0);
                s[nt][2] = ex2(s[nt][2] - mn1);
                s[nt][3] = ex2(s[nt][3] - mn1);
                rs0 += s[nt][0] + s[nt][1];
                rs1 += s[nt][2] + s[nt][3];
            }
            rs0 += __shfl_xor_sync(0xffffffffu, rs0, 1);
            rs0 += __shfl_xor_sync(0xffffffffu, rs0, 2);
            rs1 += __shfl_xor_sync(0xffffffffu, rs1, 1);
            rs1 += __shfl_xor_sync(0xffffffffu, rs1, 2);
            l0 = l0 * c0 + rs0;
            l1 = l1 * c1 + rs1;
#pragma unroll
            for (int dt = 0; dt < 8; ++dt) {
                o[dt][0] *= c0; o[dt][1] *= c0;
                o[dt][2] *= c1; o[dt][3] *= c1;
            }
        }

        // O += P @ V : P A-fragments = packed S C-fragments (free), V via ldsm
#pragma unroll
        for (int kk = 0; kk < 4; ++kk) {
            unsigned a0 = h2(s[2 * kk][0], s[2 * kk][1]);
            unsigned a1 = h2(s[2 * kk][2], s[2 * kk][3]);
            unsigned a2 = h2(s[2 * kk + 1][0], s[2 * kk + 1][1]);
            unsigned a3 = h2(s[2 * kk + 1][2], s[2 * kk + 1][3]);
#pragma unroll
            for (int dtp = 0; dtp < 4; ++dtp) {
                int n = dtp * 16 + lrow;               // n = d row in V^T
                int ch = (2 * kk + lhi) ^ (n & 7);
                unsigned b0, b1, b2, b3;
                ldsm4(b0, b1, b2, b3, vbuf + (unsigned)(n * 128 + 16 * ch));
                mma_f16(o[2 * dtp + 0], a0, a1, a2, a3, b0, b2);
                mma_f16(o[2 * dtp + 1], a0, a1, a2, a3, b1, b3);
            }
        }
    }

    // epilogue: normalize, fp16 output for proj GEMM
    {
        float inv0 = 1.0f / l0, inv1 = 1.0f / l1;
        int row0 = b * 1024 + qt * 128 + 16 * w + (lane >> 2);
        __half* ob = aout + (long)row0 * 1024 + h * 64;
#pragma unroll
        for (int dt = 0; dt < 8; ++dt) {
            int c = dt * 8 + 2 * (lane & 3);
            *(unsigned*)&ob[c] = h2(o[dt][0] * inv0, o[dt][1] * inv0);
            *(unsigned*)&ob[(long)8 * 1024 + c] = h2(o[dt][2] * inv1, o[dt][3] * inv1);
        }
    }
}

// ---------------------------------------------------------------------------
extern "C" void kernel_launch(void* const* d_in, const int* in_sizes, int n_in,
                              void* d_out, int out_size)
{
    const float* x      = (const float*)d_in[0];
    const float* past   = (const float*)d_in[1];
    const float* w_attn = (const float*)d_in[2];
    const float* b_attn = (const float*)d_in[3];
    const float* w_proj = (const float*)d_in[4];
    const float* b_proj = (const float*)d_in[5];

    float* out = (float*)d_out;
    float* present = out + 4194304;

    __half *qh_p, *ah_p, *kh_p, *vth_p, *xh_p, *wath_p, *wprh_p;
    cudaGetSymbolAddress((void**)&qh_p, g_qh);
    cudaGetSymbolAddress((void**)&ah_p, g_ah);
    cudaGetSymbolAddress((void**)&kh_p, g_kh);
    cudaGetSymbolAddress((void**)&vth_p, g_vth);
    cudaGetSymbolAddress((void**)&xh_p, g_xh);
    cudaGetSymbolAddress((void**)&wath_p, g_wath);
    cudaGetSymbolAddress((void**)&wprh_p, g_wprh);

    // 0) convert x to fp16; round+transpose weights to fp16 [N][K]
    round_half_kernel<<<4096, 256>>>(x, xh_p);
    {
        dim3 g(3072 / 32, 1024 / 32);
        round_transpose_half_kernel<<<g, 256>>>(w_attn, wath_p, 1024, 3072);
    }
    {
        dim3 g(1024 / 32, 1024 / 32);
        round_transpose_half_kernel<<<g, 256>>>(w_proj, wprh_p, 1024, 1024);
    }

    // 1) QKV projection with fused Q-scale / present / K / V^T epilogue
    {
        dim3 grid(3072 / 128, 4096 / 128);
        gemm6_kernel<<<grid, 128>>>(xh_p, wath_p, b_attn, qh_p,
                                    present, kh_p, vth_p, 1024, 1);
    }

    // 2) past half of present / K / V^T
    copy_past_kernel<<<2097152 / 256, 256>>>(past, present, kh_p, vth_p);

    // 3) attention
    attn_kernel<<<512, 256>>>(qh_p, kh_p, vth_p, ah_p);

    // 4) output projection
    {
        dim3 grid(1024 / 128, 4096 / 128);
        gemm6_kernel<<<grid, 128>>>(ah_p, wprh_p, b_proj, out,
                                    nullptr, nullptr, nullptr, 1024, 0);
    }
}